// round 7
// baseline (speedup 1.0000x reference)
#include <cuda_runtime.h>
#include <cuda_bf16.h>
#include <cstdint>

// Problem constants (fixed: T=128, B=64, D=4096, K_BITS=128)
#define N_ROWS 8192
#define DIMK   4096

// GEMM tiling: per block M=64 rows, N=128 (all bits), K-chunk 64. 512 threads.
#define BM 64
#define NTHR 512
#define KT 64
#define SKB 144                        // smem row stride bytes (72 bf16; conflict-free LDSM)
#define L_STAGE (BM * SKB)             // 9216 B
#define A_STAGE (128 * SKB)            // 18432 B
#define A_BASE  (2 * L_STAGE)          // 18432
#define NSTG 4                         // B ring depth
#define WSM_OFF (A_BASE + NSTG * A_STAGE) // 92160
#define SMEM_BYTES (WSM_OFF + 1024)    // 93184 (dynamic)
#define CS_STRIDE 132                  // padded fp32 C stride (aliases ring)

// Scratch (device globals; no allocation allowed)
__device__ uint4         g_keys[N_ROWS];
__device__ unsigned      g_hash[N_ROWS];
__device__ int           g_cnt[N_ROWS];
__device__ __nv_bfloat16 g_Abf[128 * DIMK];

#define CP_ASYNC16(sa, ga) asm volatile("cp.async.cg.shared.global [%0], [%1], 16;\n" :: "r"(sa), "l"(ga))
#define CP_COMMIT()        asm volatile("cp.async.commit_group;\n" ::)
#define CP_WAIT2()         asm volatile("cp.async.wait_group 2;\n" ::)

__device__ __forceinline__ void ldsm4(unsigned &r0, unsigned &r1, unsigned &r2, unsigned &r3, unsigned addr) {
    asm volatile("ldmatrix.sync.aligned.m8n8.x4.shared.b16 {%0,%1,%2,%3}, [%4];\n"
                 : "=r"(r0), "=r"(r1), "=r"(r2), "=r"(r3) : "r"(addr));
}

__device__ __forceinline__ void mma_bf16(float c[4], const unsigned a[4], unsigned b0, unsigned b1) {
    asm volatile(
        "mma.sync.aligned.m16n8k16.row.col.f32.bf16.bf16.f32 "
        "{%0,%1,%2,%3}, {%4,%5,%6,%7}, {%8,%9}, {%0,%1,%2,%3};\n"
        : "+f"(c[0]), "+f"(c[1]), "+f"(c[2]), "+f"(c[3])
        : "r"(a[0]), "r"(a[1]), "r"(a[2]), "r"(a[3]), "r"(b0), "r"(b1));
}

// Stage 0: pre-convert fixed projection A to bf16 (3 MB traffic).
__global__ void convertA_kernel(const float* __restrict__ A) {
    int i = blockIdx.x * 256 + threadIdx.x;   // over 128*4096/4 float4
    float4 v = reinterpret_cast<const float4*>(A)[i];
    __nv_bfloat162 h0 = __floats2bfloat162_rn(v.x, v.y);
    __nv_bfloat162 h1 = __floats2bfloat162_rn(v.z, v.w);
    uint2 p;
    p.x = reinterpret_cast<unsigned&>(h0);
    p.y = reinterpret_cast<unsigned&>(h1);
    reinterpret_cast<uint2*>(g_Abf)[i] = p;
}

// Stage 1: bf16 TC GEMM [64 x 128] per block -> sign-pack 128-bit keys + hash.
// Depth-3 pipelining: 4-stage cp.async ring for A (wait_group 2);
// latent via 3 register buffers (LDG issued 3 slabs ahead of consumption).
__global__ __launch_bounds__(NTHR, 1)
void gemm_sign_kernel(const float* __restrict__ lat) {
    extern __shared__ __align__(16) char smem[];
    const unsigned sbase = (unsigned)__cvta_generic_to_shared(smem);

    const int tid  = threadIdx.x;
    const int lane = tid & 31;
    const int wid  = tid >> 5;       // 16 warps
    const int wm   = wid & 3;        // m tile (4 x 16 rows)
    const int wn   = wid >> 2;       // n tile (4 x 32 cols)
    const int rowBase = blockIdx.x * BM;

    // zero visit counters for this block's rows (graph-replay safe)
    if (tid < BM) g_cnt[rowBase + tid] = 0;

    float acc[4][4];
#pragma unroll
    for (int n = 0; n < 4; n++)
#pragma unroll
        for (int c = 0; c < 4; c++) acc[n][c] = 0.f;

    // --- per-thread cp.async coords for A (128 rows x 64 bf16 = 16KB/chunk) ---
    unsigned aso[2];
    const __nv_bfloat16* agb[2];
#pragma unroll
    for (int q = 0; q < 2; q++) {
        int f = tid + NTHR * q;        // 1024 x 16B chunks, 8 per row
        int row = f >> 3, ch = f & 7;
        aso[q] = sbase + A_BASE + row * SKB + ch * 16;
        agb[q] = g_Abf + (size_t)row * DIMK + ch * 8;
    }
#define ISSUE_A(slab) do { \
        unsigned _st = ((slab) & 3) * A_STAGE; \
        _Pragma("unroll") for (int q = 0; q < 2; q++) \
            CP_ASYNC16(aso[q] + _st, agb[q] + (size_t)(slab) * KT); \
        CP_COMMIT(); } while (0)

    // --- per-thread latent load coords (64 rows x 64 fp32 = 1024 float4) ---
    size_t   lgo[2];
    unsigned lso[2];
#pragma unroll
    for (int q = 0; q < 2; q++) {
        int f = tid + NTHR * q;        // 16 float4 per row
        int r = f >> 4, c = f & 15;
        lgo[q] = (size_t)(rowBase + r) * DIMK + c * 4;
        lso[q] = r * SKB + c * 8;      // byte offset within L stage
    }

    // --- prologue: A slabs 0..2 in flight; latent slabs 0..2 in regs ---
    ISSUE_A(0); ISSUE_A(1); ISSUE_A(2);
    float4 rl[3][2];
#pragma unroll
    for (int s = 0; s < 3; s++)
#pragma unroll
        for (int q = 0; q < 2; q++)
            rl[s][q] = *reinterpret_cast<const float4*>(&lat[lgo[q] + (size_t)s * KT]);

    // ldmatrix base addresses (lane-dependent; stage offset added per iter)
    const unsigned lmb = sbase + (wm * 16 + (lane & 15)) * SKB + (lane >> 4) * 16;
    const unsigned amb = sbase + A_BASE
                       + (wn * 32 + (lane & 7) + ((lane >> 4) << 3)) * SKB
                       + ((lane >> 3) & 1) * 16;

    const int NC = DIMK / KT;  // 64
    int rb = 0;                // latent reg-buffer index = kc % 3
    for (int kc = 0; kc < NC; kc++) {
        // convert + store latent slab kc (LDG issued 3 iters ago; latency hidden)
        char* Ls = smem + (kc & 1) * L_STAGE;
#pragma unroll
        for (int q = 0; q < 2; q++) {
            __nv_bfloat162 h0 = __floats2bfloat162_rn(rl[rb][q].x, rl[rb][q].y);
            __nv_bfloat162 h1 = __floats2bfloat162_rn(rl[rb][q].z, rl[rb][q].w);
            uint2 pv;
            pv.x = reinterpret_cast<unsigned&>(h0);
            pv.y = reinterpret_cast<unsigned&>(h1);
            *reinterpret_cast<uint2*>(Ls + lso[q]) = pv;
        }
        CP_WAIT2();          // committed ..kc+2; <=2 pending -> A slab kc resident
        __syncthreads();     // also: all LDSM of slab kc-1 complete

        // issue A slab kc+3 into stage (kc+3)&3 = (kc-1)&3, last read by MMA(kc-1)
        if (kc + 3 < NC) ISSUE_A(kc + 3);
        else             CP_COMMIT();          // keep group accounting invariant
        // latent slab kc+3 into the reg buffer just drained by the STS above
        if (kc + 3 < NC) {
            const size_t k0 = (size_t)(kc + 3) * KT;
#pragma unroll
            for (int q = 0; q < 2; q++)
                rl[rb][q] = *reinterpret_cast<const float4*>(&lat[lgo[q] + k0]);
        }
        rb = (rb == 2) ? 0 : rb + 1;

        const unsigned lb = lmb + (kc & 1) * L_STAGE;
        const unsigned ab = amb + (kc & 3) * A_STAGE;
#pragma unroll
        for (int ks = 0; ks < 4; ks++) {
            unsigned a[4], b0[4], b1[4];
            ldsm4(a[0], a[1], a[2], a[3], lb + ks * 32);
            ldsm4(b0[0], b0[1], b0[2], b0[3], ab + ks * 32);
            ldsm4(b1[0], b1[1], b1[2], b1[3], ab + 16 * SKB + ks * 32);
            mma_bf16(acc[0], a, b0[0], b0[1]);
            mma_bf16(acc[1], a, b0[2], b0[3]);
            mma_bf16(acc[2], a, b1[0], b1[1]);
            mma_bf16(acc[3], a, b1[2], b1[3]);
        }
        // no tail sync: next STS targets the other L stage; A issue ordered by next sync
    }
    __syncthreads();   // all MMA smem reads done before aliasing C over the buffers

    // --- epilogue: C -> smem (padded), ballot sign-pack, key + hash ---
    float*    Cs  = reinterpret_cast<float*>(smem);
    unsigned* wsm = reinterpret_cast<unsigned*>(smem + WSM_OFF);
    const int g = lane >> 2, tig = lane & 3;
#pragma unroll
    for (int ni = 0; ni < 4; ni++) {
        int row = wm * 16 + g;
        int col = wn * 32 + ni * 8 + 2 * tig;
        *reinterpret_cast<float2*>(&Cs[row * CS_STRIDE + col])       = make_float2(acc[ni][0], acc[ni][1]);
        *reinterpret_cast<float2*>(&Cs[(row + 8) * CS_STRIDE + col]) = make_float2(acc[ni][2], acc[ni][3]);
    }
    __syncthreads();

    // 256 words (64 rows x 4); 16 warps x 16 words; ballot packs 32 signs/instr
#pragma unroll
    for (int t = 0; t < 16; t++) {
        int idx = wid * 16 + t;
        int row = idx >> 2, w = idx & 3;
        unsigned bits = __ballot_sync(0xffffffffu, Cs[row * CS_STRIDE + w * 32 + lane] > 0.0f);
        if (lane == 0) {
            wsm[idx] = bits;
            reinterpret_cast<unsigned*>(g_keys)[(size_t)(rowBase + row) * 4 + w] = bits;
        }
    }
    __syncthreads();

    if (tid < BM) {
        unsigned w0 = wsm[tid * 4 + 0], w1 = wsm[tid * 4 + 1];
        unsigned w2 = wsm[tid * 4 + 2], w3 = wsm[tid * 4 + 3];
        unsigned h = w0 * 0x9E3779B1u;
        h ^= w1; h *= 0x85EBCA77u;
        h ^= w2; h *= 0xC2B2AE3Du;
        h ^= w3; h *= 0x27D4EB2Fu;
        h ^= h >> 15;
        g_hash[rowBase + tid] = h;
    }
}

// Stage 2: tile-parallel prefix-duplicate count (lower-triangle 256x256 tiles).
#define TI 256
__global__ __launch_bounds__(TI, 8)
void count_tile_kernel() {
    const int ti = blockIdx.y, tj = blockIdx.x;
    if (tj > ti) return;

    __shared__ __align__(16) unsigned shh[TI];
    const int tid   = threadIdx.x;
    const int i     = ti * TI + tid;
    const int jbase = tj * TI;

    shh[tid] = g_hash[jbase + tid];
    const unsigned hi = g_hash[i];
    const uint4    ki = g_keys[i];
    __syncthreads();

    const int lim = (ti == tj) ? (tid + 1) : TI;
    const int l4  = lim & ~3;
    int cnt = 0;

    const uint4* sh4 = reinterpret_cast<const uint4*>(shh);
    for (int j = 0; j < l4; j += 4) {
        uint4 hv = sh4[j >> 2];
        if (hv.x == hi) { uint4 kj = g_keys[jbase + j    ]; cnt += (kj.x==ki.x && kj.y==ki.y && kj.z==ki.z && kj.w==ki.w); }
        if (hv.y == hi) { uint4 kj = g_keys[jbase + j + 1]; cnt += (kj.x==ki.x && kj.y==ki.y && kj.z==ki.z && kj.w==ki.w); }
        if (hv.z == hi) { uint4 kj = g_keys[jbase + j + 2]; cnt += (kj.x==ki.x && kj.y==ki.y && kj.z==ki.z && kj.w==ki.w); }
        if (hv.w == hi) { uint4 kj = g_keys[jbase + j + 3]; cnt += (kj.x==ki.x && kj.y==ki.y && kj.z==ki.z && kj.w==ki.w); }
    }
    for (int j = l4; j < lim; j++) {
        if (shh[j] == hi) {
            uint4 kj = g_keys[jbase + j];
            cnt += (kj.x==ki.x && kj.y==ki.y && kj.z==ki.z && kj.w==ki.w);
        }
    }

    if (cnt) atomicAdd(&g_cnt[i], cnt);
}

// Stage 3: finalize — intrinsic reward.
__global__ void finalize_kernel(float* __restrict__ out) {
    int i = blockIdx.x * 256 + threadIdx.x;
    out[i] = rsqrtf((float)g_cnt[i]);
}

extern "C" void kernel_launch(void* const* d_in, const int* in_sizes, int n_in,
                              void* d_out, int out_size) {
    const float* lat  = (const float*)d_in[0];   // [128,64,4096]
    const float* Amat = (const float*)d_in[1];   // [128,4096]
    float* out = (float*)d_out;                  // [T,B] fp32

    cudaFuncSetAttribute(gemm_sign_kernel,
                         cudaFuncAttributeMaxDynamicSharedMemorySize, SMEM_BYTES);

    convertA_kernel<<<(128 * DIMK / 4) / 256, 256>>>(Amat);
    gemm_sign_kernel<<<N_ROWS / BM, NTHR, SMEM_BYTES>>>(lat);
    dim3 cgrid(N_ROWS / TI, N_ROWS / TI);
    count_tile_kernel<<<cgrid, TI>>>();
    finalize_kernel<<<N_ROWS / 256, 256>>>(out);
}

// round 8
// speedup vs baseline: 1.0344x; 1.0344x over previous
#include <cuda_runtime.h>
#include <cuda_bf16.h>
#include <cstdint>

// Problem constants (fixed: T=128, B=64, D=4096, K_BITS=128)
#define N_ROWS 8192
#define DIMK   4096

// GEMM tiling: per block M=64 rows, N=128 bits, K-chunk 64. 256 threads, warp tile 32x32.
#define BM 64
#define NTHR 256
#define KT 64
#define SKB 144                        // smem row stride bytes (72 bf16; conflict-free LDSM)
#define L_STAGE (BM * SKB)             // 9216 B
#define A_STAGE (128 * SKB)            // 18432 B
#define A_BASE  (2 * L_STAGE)          // 18432
#define NSTG 3                         // A ring depth
#define WSM_OFF (A_BASE + NSTG * A_STAGE) // 73728
#define SMEM_BYTES (WSM_OFF + 1024)    // 74752 (dynamic)
#define CS_STRIDE 132                  // padded fp32 C stride (aliases ring)

// Scratch (device globals; no allocation allowed)
__device__ uint4         g_keys[N_ROWS];
__device__ unsigned      g_hash[N_ROWS];
__device__ int           g_cnt[N_ROWS];
__device__ __nv_bfloat16 g_Abf[128 * DIMK];

#define CP_ASYNC16(sa, ga) asm volatile("cp.async.cg.shared.global [%0], [%1], 16;\n" :: "r"(sa), "l"(ga))
#define CP_COMMIT()        asm volatile("cp.async.commit_group;\n" ::)
#define CP_WAIT1()         asm volatile("cp.async.wait_group 1;\n" ::)

__device__ __forceinline__ void ldsm4(unsigned r[4], unsigned addr) {
    asm volatile("ldmatrix.sync.aligned.m8n8.x4.shared.b16 {%0,%1,%2,%3}, [%4];\n"
                 : "=r"(r[0]), "=r"(r[1]), "=r"(r[2]), "=r"(r[3]) : "r"(addr));
}

__device__ __forceinline__ void mma_bf16(float c[4], const unsigned a[4], unsigned b0, unsigned b1) {
    asm volatile(
        "mma.sync.aligned.m16n8k16.row.col.f32.bf16.bf16.f32 "
        "{%0,%1,%2,%3}, {%4,%5,%6,%7}, {%8,%9}, {%0,%1,%2,%3};\n"
        : "+f"(c[0]), "+f"(c[1]), "+f"(c[2]), "+f"(c[3])
        : "r"(a[0]), "r"(a[1]), "r"(a[2]), "r"(a[3]), "r"(b0), "r"(b1));
}

// Stage 0: pre-convert fixed projection A to bf16 (3 MB traffic).
__global__ void convertA_kernel(const float* __restrict__ A) {
    int i = blockIdx.x * 256 + threadIdx.x;   // over 128*4096/4 float4
    float4 v = reinterpret_cast<const float4*>(A)[i];
    __nv_bfloat162 h0 = __floats2bfloat162_rn(v.x, v.y);
    __nv_bfloat162 h1 = __floats2bfloat162_rn(v.z, v.w);
    uint2 p;
    p.x = reinterpret_cast<unsigned&>(h0);
    p.y = reinterpret_cast<unsigned&>(h1);
    reinterpret_cast<uint2*>(g_Abf)[i] = p;
}

// Stage 1: bf16 TC GEMM [64 x 128] per block -> sign-pack 128-bit keys + hash.
// 256 threads, 8 warps of 32x32 tiles (halves B-fragment smem traffic vs 16x32).
// A: 3-stage cp.async ring (wait_group 1, issued 2 slabs ahead).
// Latent: depth-2 register prefetch (fits in regs at 256 threads; no spills).
__global__ __launch_bounds__(NTHR, 1)
void gemm_sign_kernel(const float* __restrict__ lat) {
    extern __shared__ __align__(16) char smem[];
    const unsigned sbase = (unsigned)__cvta_generic_to_shared(smem);

    const int tid  = threadIdx.x;
    const int lane = tid & 31;
    const int wid  = tid >> 5;       // 8 warps
    const int wm   = wid & 1;        // 2 m tiles of 32 rows
    const int wn   = wid >> 1;       // 4 n tiles of 32 cols
    const int rowBase = blockIdx.x * BM;

    // zero visit counters for this block's rows (graph-replay safe)
    if (tid < BM) g_cnt[rowBase + tid] = 0;

    float acc[2][4][4];
#pragma unroll
    for (int mi = 0; mi < 2; mi++)
#pragma unroll
        for (int n = 0; n < 4; n++)
#pragma unroll
            for (int c = 0; c < 4; c++) acc[mi][n][c] = 0.f;

    // --- per-thread cp.async coords for A (128 rows x 64 bf16 = 16KB/slab) ---
    unsigned aso[4];
    const __nv_bfloat16* agb[4];
#pragma unroll
    for (int q = 0; q < 4; q++) {
        int f = tid + NTHR * q;        // 1024 x 16B chunks, 8 per row
        int row = f >> 3, ch = f & 7;
        aso[q] = sbase + A_BASE + row * SKB + ch * 16;
        agb[q] = g_Abf + (size_t)row * DIMK + ch * 8;
    }
#define ISSUE_A(slab) do { \
        unsigned _st = ((slab) % 3) * A_STAGE; \
        _Pragma("unroll") for (int q = 0; q < 4; q++) \
            CP_ASYNC16(aso[q] + _st, agb[q] + (size_t)(slab) * KT); \
        CP_COMMIT(); } while (0)

    // --- per-thread latent load coords (64 rows x 64 fp32 = 1024 float4) ---
    size_t   lgo[4];
    unsigned lso[4];
#pragma unroll
    for (int q = 0; q < 4; q++) {
        int f = tid + NTHR * q;        // 16 float4 per row
        int r = f >> 4, c = f & 15;
        lgo[q] = (size_t)(rowBase + r) * DIMK + c * 4;
        lso[q] = r * SKB + c * 8;      // byte offset within L stage
    }

    // --- prologue: A slabs 0,1 in flight; latent slabs 0,1 in regs ---
    ISSUE_A(0); ISSUE_A(1);
    float4 rl[2][4];
#pragma unroll
    for (int s = 0; s < 2; s++)
#pragma unroll
        for (int q = 0; q < 4; q++)
            rl[s][q] = *reinterpret_cast<const float4*>(&lat[lgo[q] + (size_t)s * KT]);

    // ldmatrix base addresses (lane-dependent; stage offset added per iter)
    const unsigned lmb = sbase + (wm * 32 + (lane & 15)) * SKB + (lane >> 4) * 16;
    const unsigned amb = sbase + A_BASE
                       + (wn * 32 + (lane & 7) + ((lane >> 4) << 3)) * SKB
                       + ((lane >> 3) & 1) * 16;

    const int NC = DIMK / KT;  // 64
    for (int kc = 0; kc < NC; kc++) {
        const int ls = kc & 1;
        // convert + store latent slab kc (LDG issued 2 iters ago)
        char* Ls = smem + ls * L_STAGE;
#pragma unroll
        for (int q = 0; q < 4; q++) {
            __nv_bfloat162 h0 = __floats2bfloat162_rn(rl[ls][q].x, rl[ls][q].y);
            __nv_bfloat162 h1 = __floats2bfloat162_rn(rl[ls][q].z, rl[ls][q].w);
            uint2 pv;
            pv.x = reinterpret_cast<unsigned&>(h0);
            pv.y = reinterpret_cast<unsigned&>(h1);
            *reinterpret_cast<uint2*>(Ls + lso[q]) = pv;
        }
        CP_WAIT1();          // groups 0..kc+1 committed; <=1 pending -> A slab kc resident
        __syncthreads();     // + all LDSM of slab kc-1 complete

        if (kc + 2 < NC) {
            // A stage (kc+2)%3 last read by MMA(kc-1), done before this sync
            ISSUE_A(kc + 2);
            // latent slab kc+2 into the reg buffer drained by the STS above
            const size_t k0 = (size_t)(kc + 2) * KT;
#pragma unroll
            for (int q = 0; q < 4; q++)
                rl[ls][q] = *reinterpret_cast<const float4*>(&lat[lgo[q] + k0]);
        } else {
            CP_COMMIT();     // keep group accounting invariant
        }

        const unsigned lb = lmb + ls * L_STAGE;
        const unsigned ab = amb + (kc % 3) * A_STAGE;
#pragma unroll
        for (int ks = 0; ks < 4; ks++) {
            unsigned a0[4], a1[4], b0[4], b1[4];
            ldsm4(a0, lb + ks * 32);                 // rows wm*32 +  0..15
            ldsm4(a1, lb + 16 * SKB + ks * 32);      // rows wm*32 + 16..31
            ldsm4(b0, ab + ks * 32);                 // cols wn*32 +  0..15
            ldsm4(b1, ab + 16 * SKB + ks * 32);      // cols wn*32 + 16..31
            mma_bf16(acc[0][0], a0, b0[0], b0[1]);
            mma_bf16(acc[0][1], a0, b0[2], b0[3]);
            mma_bf16(acc[0][2], a0, b1[0], b1[1]);
            mma_bf16(acc[0][3], a0, b1[2], b1[3]);
            mma_bf16(acc[1][0], a1, b0[0], b0[1]);
            mma_bf16(acc[1][1], a1, b0[2], b0[3]);
            mma_bf16(acc[1][2], a1, b1[0], b1[1]);
            mma_bf16(acc[1][3], a1, b1[2], b1[3]);
        }
        // no tail sync: next STS targets the other L stage; A issue ordered by next sync
    }
    __syncthreads();   // all MMA smem reads done before aliasing C over the buffers

    // --- epilogue: C -> smem (padded), ballot sign-pack, key + hash ---
    float*    Cs  = reinterpret_cast<float*>(smem);
    unsigned* wsm = reinterpret_cast<unsigned*>(smem + WSM_OFF);
    const int g = lane >> 2, tig = lane & 3;
#pragma unroll
    for (int mi = 0; mi < 2; mi++) {
#pragma unroll
        for (int ni = 0; ni < 4; ni++) {
            int row = wm * 32 + mi * 16 + g;
            int col = wn * 32 + ni * 8 + 2 * tig;
            *reinterpret_cast<float2*>(&Cs[row * CS_STRIDE + col])       = make_float2(acc[mi][ni][0], acc[mi][ni][1]);
            *reinterpret_cast<float2*>(&Cs[(row + 8) * CS_STRIDE + col]) = make_float2(acc[mi][ni][2], acc[mi][ni][3]);
        }
    }
    __syncthreads();

    // 256 words (64 rows x 4); 8 warps x 32 words; ballot packs 32 signs/instr
#pragma unroll
    for (int t = 0; t < 32; t++) {
        int idx = wid * 32 + t;
        int row = idx >> 2, w = idx & 3;
        unsigned bits = __ballot_sync(0xffffffffu, Cs[row * CS_STRIDE + w * 32 + lane] > 0.0f);
        if (lane == 0) {
            wsm[idx] = bits;
            reinterpret_cast<unsigned*>(g_keys)[(size_t)(rowBase + row) * 4 + w] = bits;
        }
    }
    __syncthreads();

    if (tid < BM) {
        unsigned w0 = wsm[tid * 4 + 0], w1 = wsm[tid * 4 + 1];
        unsigned w2 = wsm[tid * 4 + 2], w3 = wsm[tid * 4 + 3];
        unsigned h = w0 * 0x9E3779B1u;
        h ^= w1; h *= 0x85EBCA77u;
        h ^= w2; h *= 0xC2B2AE3Du;
        h ^= w3; h *= 0x27D4EB2Fu;
        h ^= h >> 15;
        g_hash[rowBase + tid] = h;
    }
}

// Stage 2: tile-parallel prefix-duplicate count (lower-triangle 256x256 tiles).
#define TI 256
__global__ __launch_bounds__(TI, 8)
void count_tile_kernel() {
    const int ti = blockIdx.y, tj = blockIdx.x;
    if (tj > ti) return;

    __shared__ __align__(16) unsigned shh[TI];
    const int tid   = threadIdx.x;
    const int i     = ti * TI + tid;
    const int jbase = tj * TI;

    shh[tid] = g_hash[jbase + tid];
    const unsigned hi = g_hash[i];
    const uint4    ki = g_keys[i];
    __syncthreads();

    const int lim = (ti == tj) ? (tid + 1) : TI;
    const int l4  = lim & ~3;
    int cnt = 0;

    const uint4* sh4 = reinterpret_cast<const uint4*>(shh);
    for (int j = 0; j < l4; j += 4) {
        uint4 hv = sh4[j >> 2];
        if (hv.x == hi) { uint4 kj = g_keys[jbase + j    ]; cnt += (kj.x==ki.x && kj.y==ki.y && kj.z==ki.z && kj.w==ki.w); }
        if (hv.y == hi) { uint4 kj = g_keys[jbase + j + 1]; cnt += (kj.x==ki.x && kj.y==ki.y && kj.z==ki.z && kj.w==ki.w); }
        if (hv.z == hi) { uint4 kj = g_keys[jbase + j + 2]; cnt += (kj.x==ki.x && kj.y==ki.y && kj.z==ki.z && kj.w==ki.w); }
        if (hv.w == hi) { uint4 kj = g_keys[jbase + j + 3]; cnt += (kj.x==ki.x && kj.y==ki.y && kj.z==ki.z && kj.w==ki.w); }
    }
    for (int j = l4; j < lim; j++) {
        if (shh[j] == hi) {
            uint4 kj = g_keys[jbase + j];
            cnt += (kj.x==ki.x && kj.y==ki.y && kj.z==ki.z && kj.w==ki.w);
        }
    }

    if (cnt) atomicAdd(&g_cnt[i], cnt);
}

// Stage 3: finalize — intrinsic reward.
__global__ void finalize_kernel(float* __restrict__ out) {
    int i = blockIdx.x * 256 + threadIdx.x;
    out[i] = rsqrtf((float)g_cnt[i]);
}

extern "C" void kernel_launch(void* const* d_in, const int* in_sizes, int n_in,
                              void* d_out, int out_size) {
    const float* lat  = (const float*)d_in[0];   // [128,64,4096]
    const float* Amat = (const float*)d_in[1];   // [128,4096]
    float* out = (float*)d_out;                  // [T,B] fp32

    cudaFuncSetAttribute(gemm_sign_kernel,
                         cudaFuncAttributeMaxDynamicSharedMemorySize, SMEM_BYTES);

    convertA_kernel<<<(128 * DIMK / 4) / 256, 256>>>(Amat);
    gemm_sign_kernel<<<N_ROWS / BM, NTHR, SMEM_BYTES>>>(lat);
    dim3 cgrid(N_ROWS / TI, N_ROWS / TI);
    count_tile_kernel<<<cgrid, TI>>>();
    finalize_kernel<<<N_ROWS / 256, 256>>>(out);
}

// round 11
// speedup vs baseline: 1.5428x; 1.4915x over previous
#include <cuda_runtime.h>
#include <cuda_bf16.h>
#include <cstdint>

// Problem constants (fixed: T=128, B=64, D=4096, K_BITS=128)
#define N_ROWS 8192
#define DIMK   4096

// GEMM tiling: per block M=64 rows, N=128 bits, K-chunk 128. 512 threads, 16 warps 16x32.
#define BM 64
#define NTHR 512
#define KT 128
#define SKB 272                        // smem row stride bytes (256B data + 16 pad; conflict-free LDSM)
#define L_STAGE (BM * SKB)             // 17408 B
#define A_STAGE (128 * SKB)            // 34816 B
#define A_BASE  (2 * L_STAGE)          // 34816
#define WSM_OFF (A_BASE + 2 * A_STAGE) // 104448
#define SMEM_BYTES (WSM_OFF + 1024)    // 105472 (dynamic)
#define CS_STRIDE 132                  // padded fp32 C stride (aliases ring)

// Scratch (device globals; no allocation allowed)
__device__ uint4         g_keys[N_ROWS];
__device__ unsigned      g_hash[N_ROWS];
__device__ int           g_cnt[N_ROWS];
__device__ __nv_bfloat16 g_Abf[128 * DIMK];

#define CP_ASYNC16(sa, ga) asm volatile("cp.async.cg.shared.global [%0], [%1], 16;\n" :: "r"(sa), "l"(ga))
#define CP_COMMIT()        asm volatile("cp.async.commit_group;\n" ::)
#define CP_WAIT0()         asm volatile("cp.async.wait_group 0;\n" ::)

__device__ __forceinline__ void ldsm4(unsigned r[4], unsigned addr) {
    asm volatile("ldmatrix.sync.aligned.m8n8.x4.shared.b16 {%0,%1,%2,%3}, [%4];\n"
                 : "=r"(r[0]), "=r"(r[1]), "=r"(r[2]), "=r"(r[3]) : "r"(addr));
}

__device__ __forceinline__ void mma_bf16(float c[4], const unsigned a[4], unsigned b0, unsigned b1) {
    asm volatile(
        "mma.sync.aligned.m16n8k16.row.col.f32.bf16.bf16.f32 "
        "{%0,%1,%2,%3}, {%4,%5,%6,%7}, {%8,%9}, {%0,%1,%2,%3};\n"
        : "+f"(c[0]), "+f"(c[1]), "+f"(c[2]), "+f"(c[3])
        : "r"(a[0]), "r"(a[1]), "r"(a[2]), "r"(a[3]), "r"(b0), "r"(b1));
}

// Stage 0: pre-convert fixed projection A to bf16 (proven version).
__global__ void convertA_kernel(const float* __restrict__ A) {
    int i = blockIdx.x * 256 + threadIdx.x;   // over 128*4096/4 float4
    float4 v = reinterpret_cast<const float4*>(A)[i];
    __nv_bfloat162 h0 = __floats2bfloat162_rn(v.x, v.y);
    __nv_bfloat162 h1 = __floats2bfloat162_rn(v.z, v.w);
    uint2 p;
    p.x = reinterpret_cast<unsigned&>(h0);
    p.y = reinterpret_cast<unsigned&>(h1);
    reinterpret_cast<uint2*>(g_Abf)[i] = p;
}

// Stage 1: bf16 TC GEMM [64 x 128] per block -> sign-pack 128-bit keys + hash.
// R5 schedule (depth-1, 2-stage ring, per-iter sync) with KT=128: half the iterations.
__global__ __launch_bounds__(NTHR, 1)
void gemm_sign_kernel(const float* __restrict__ lat) {
    extern __shared__ __align__(16) char smem[];
    const unsigned sbase = (unsigned)__cvta_generic_to_shared(smem);

    const int tid  = threadIdx.x;
    const int lane = tid & 31;
    const int wid  = tid >> 5;       // 16 warps
    const int wm   = wid & 3;        // m tile (4 x 16 rows)
    const int wn   = wid >> 2;       // n tile (4 x 32 cols)
    const int rowBase = blockIdx.x * BM;

    // zero visit counters for this block's rows (graph-replay safe)
    if (tid < BM) g_cnt[rowBase + tid] = 0;

    float acc[4][4];
#pragma unroll
    for (int n = 0; n < 4; n++)
#pragma unroll
        for (int c = 0; c < 4; c++) acc[n][c] = 0.f;

    // --- per-thread cp.async coords for A (128 rows x 128 bf16 = 32KB/slab) ---
    unsigned aso[4];
    const __nv_bfloat16* agb[4];
#pragma unroll
    for (int q = 0; q < 4; q++) {
        int f = tid + NTHR * q;        // 2048 x 16B chunks, 16 per row
        int row = f >> 4, ch = f & 15;
        aso[q] = sbase + A_BASE + row * SKB + ch * 16;
        agb[q] = g_Abf + (size_t)row * DIMK + ch * 8;
    }
#define ISSUE_A(slab) do { \
        unsigned _st = ((slab) & 1) * A_STAGE; \
        _Pragma("unroll") for (int q = 0; q < 4; q++) \
            CP_ASYNC16(aso[q] + _st, agb[q] + (size_t)(slab) * KT); \
        CP_COMMIT(); } while (0)

    // --- per-thread latent load coords (64 rows x 128 fp32 = 2048 float4) ---
    const char* latb = reinterpret_cast<const char*>(lat);
    unsigned lgo[4], lso[4];
#pragma unroll
    for (int q = 0; q < 4; q++) {
        int f = tid + NTHR * q;        // 32 float4 per row
        int r = f >> 5, c = f & 31;
        lgo[q] = (unsigned)(((rowBase + r) * DIMK + c * 4) * 4);   // byte offset (fits 32-bit)
        lso[q] = r * SKB + c * 8;      // bf16 byte offset: chunk c -> 8 bytes (BUGFIX: was c*16)
    }

    // --- prologue: A slab 0 in flight; latent slab 0 in regs ---
    ISSUE_A(0);
    float4 rl[4];
#pragma unroll
    for (int q = 0; q < 4; q++)
        rl[q] = *reinterpret_cast<const float4*>(latb + lgo[q]);

    // ldmatrix base addresses (lane-dependent; stage offset added per iter)
    const unsigned lmb = sbase + (wm * 16 + (lane & 15)) * SKB + (lane >> 4) * 16;
    const unsigned amb = sbase + A_BASE
                       + (wn * 32 + (lane & 7) + ((lane >> 4) << 3)) * SKB
                       + ((lane >> 3) & 1) * 16;

    const int NC = DIMK / KT;  // 32
    for (int kc = 0; kc < NC; kc++) {
        const int ls = kc & 1;
        // convert + store latent slab kc
        char* Ls = smem + ls * L_STAGE;
#pragma unroll
        for (int q = 0; q < 4; q++) {
            __nv_bfloat162 h0 = __floats2bfloat162_rn(rl[q].x, rl[q].y);
            __nv_bfloat162 h1 = __floats2bfloat162_rn(rl[q].z, rl[q].w);
            uint2 pv;
            pv.x = reinterpret_cast<unsigned&>(h0);
            pv.y = reinterpret_cast<unsigned&>(h1);
            *reinterpret_cast<uint2*>(Ls + lso[q]) = pv;
        }
        CP_WAIT0();          // A slab kc resident
        __syncthreads();     // + all LDSM of slab kc-1 complete

        if (kc + 1 < NC) {
            // A stage (kc+1)&1 last read by MMA(kc-1); ordered by the sync above
            ISSUE_A(kc + 1);
            const unsigned k0 = (unsigned)(kc + 1) * KT * 4;   // byte advance
#pragma unroll
            for (int q = 0; q < 4; q++)
                rl[q] = *reinterpret_cast<const float4*>(latb + lgo[q] + k0);
        }

        const unsigned lb = lmb + ls * L_STAGE;
        const unsigned ab = amb + ls * A_STAGE;
#pragma unroll
        for (int ks = 0; ks < 8; ks++) {
            unsigned a[4], b0[4], b1[4];
            ldsm4(a,  lb + ks * 32);
            ldsm4(b0, ab + ks * 32);
            ldsm4(b1, ab + 16 * SKB + ks * 32);
            mma_bf16(acc[0], a, b0[0], b0[1]);
            mma_bf16(acc[1], a, b0[2], b0[3]);
            mma_bf16(acc[2], a, b1[0], b1[1]);
            mma_bf16(acc[3], a, b1[2], b1[3]);
        }
        // no tail sync: next STS targets the other L stage; A issue ordered by next sync
    }
    __syncthreads();   // all MMA smem reads done before aliasing C over the buffers

    // --- epilogue: C -> smem (padded), ballot sign-pack, key + hash ---
    float*    Cs  = reinterpret_cast<float*>(smem);
    unsigned* wsm = reinterpret_cast<unsigned*>(smem + WSM_OFF);
    const int g = lane >> 2, tig = lane & 3;
#pragma unroll
    for (int ni = 0; ni < 4; ni++) {
        int row = wm * 16 + g;
        int col = wn * 32 + ni * 8 + 2 * tig;
        *reinterpret_cast<float2*>(&Cs[row * CS_STRIDE + col])       = make_float2(acc[ni][0], acc[ni][1]);
        *reinterpret_cast<float2*>(&Cs[(row + 8) * CS_STRIDE + col]) = make_float2(acc[ni][2], acc[ni][3]);
    }
    __syncthreads();

    // 256 words (64 rows x 4); 16 warps x 16 words; ballot packs 32 signs/instr
#pragma unroll
    for (int t = 0; t < 16; t++) {
        int idx = wid * 16 + t;
        int row = idx >> 2, w = idx & 3;
        unsigned bits = __ballot_sync(0xffffffffu, Cs[row * CS_STRIDE + w * 32 + lane] > 0.0f);
        if (lane == 0) {
            wsm[idx] = bits;
            reinterpret_cast<unsigned*>(g_keys)[(size_t)(rowBase + row) * 4 + w] = bits;
        }
    }
    __syncthreads();

    if (tid < BM) {
        unsigned w0 = wsm[tid * 4 + 0], w1 = wsm[tid * 4 + 1];
        unsigned w2 = wsm[tid * 4 + 2], w3 = wsm[tid * 4 + 3];
        unsigned h = w0 * 0x9E3779B1u;
        h ^= w1; h *= 0x85EBCA77u;
        h ^= w2; h *= 0xC2B2AE3Du;
        h ^= w3; h *= 0x27D4EB2Fu;
        h ^= h >> 15;
        g_hash[rowBase + tid] = h;
    }
}

// Stage 2: tile-parallel prefix-duplicate count (lower-triangle 256x256 tiles).
#define TI 256
__global__ __launch_bounds__(TI, 8)
void count_tile_kernel() {
    const int ti = blockIdx.y, tj = blockIdx.x;
    if (tj > ti) return;

    __shared__ __align__(16) unsigned shh[TI];
    const int tid   = threadIdx.x;
    const int i     = ti * TI + tid;
    const int jbase = tj * TI;

    shh[tid] = g_hash[jbase + tid];
    const unsigned hi = g_hash[i];
    const uint4    ki = g_keys[i];
    __syncthreads();

    const int lim = (ti == tj) ? (tid + 1) : TI;
    const int l4  = lim & ~3;
    int cnt = 0;

    const uint4* sh4 = reinterpret_cast<const uint4*>(shh);
    for (int j = 0; j < l4; j += 4) {
        uint4 hv = sh4[j >> 2];
        if (hv.x == hi) { uint4 kj = g_keys[jbase + j    ]; cnt += (kj.x==ki.x && kj.y==ki.y && kj.z==ki.z && kj.w==ki.w); }
        if (hv.y == hi) { uint4 kj = g_keys[jbase + j + 1]; cnt += (kj.x==ki.x && kj.y==ki.y && kj.z==ki.z && kj.w==ki.w); }
        if (hv.z == hi) { uint4 kj = g_keys[jbase + j + 2]; cnt += (kj.x==ki.x && kj.y==ki.y && kj.z==ki.z && kj.w==ki.w); }
        if (hv.w == hi) { uint4 kj = g_keys[jbase + j + 3]; cnt += (kj.x==ki.x && kj.y==ki.y && kj.z==ki.z && kj.w==ki.w); }
    }
    for (int j = l4; j < lim; j++) {
        if (shh[j] == hi) {
            uint4 kj = g_keys[jbase + j];
            cnt += (kj.x==ki.x && kj.y==ki.y && kj.z==ki.z && kj.w==ki.w);
        }
    }

    if (cnt) atomicAdd(&g_cnt[i], cnt);
}

// Stage 3: finalize — intrinsic reward.
__global__ void finalize_kernel(float* __restrict__ out) {
    int i = blockIdx.x * 256 + threadIdx.x;
    out[i] = rsqrtf((float)g_cnt[i]);
}

extern "C" void kernel_launch(void* const* d_in, const int* in_sizes, int n_in,
                              void* d_out, int out_size) {
    const float* lat  = (const float*)d_in[0];   // [128,64,4096]
    const float* Amat = (const float*)d_in[1];   // [128,4096]
    float* out = (float*)d_out;                  // [T,B] fp32

    cudaFuncSetAttribute(gemm_sign_kernel,
                         cudaFuncAttributeMaxDynamicSharedMemorySize, SMEM_BYTES);

    convertA_kernel<<<(128 * DIMK / 4) / 256, 256>>>(Amat);
    gemm_sign_kernel<<<N_ROWS / BM, NTHR, SMEM_BYTES>>>(lat);
    dim3 cgrid(N_ROWS / TI, N_ROWS / TI);
    count_tile_kernel<<<cgrid, TI>>>();
    finalize_kernel<<<N_ROWS / 256, 256>>>(out);
}